// round 16
// baseline (speedup 1.0000x reference)
#include <cuda_runtime.h>
#include <math.h>
#include <stdint.h>

typedef unsigned long long ull;

#define TPB  512
#define NBLK 128
#define CSZ  4
#define NCLU 32
#define DB 512
#define DI 64
#define DH 256
#define DJ 64     /* j cols per CTA */
#define NB 16     /* batches per cluster */
#define DO 2
#define DT 200
#define HST 17    /* padded stride for h / hnew */
#define PSTR 9    /* ull stride per partial slot (bank-conflict pad) */
#define PSF 18    /* float stride per slot */

// ---------------- static device scratch ----------------
__device__ float d_wdgxT[DI*DI];
__device__ float d_wdghT[DI*DH];
__device__ float d_wxzT[DI*DH], d_wmzT[DI*DH];
__device__ float d_wxrT[DI*DH], d_wmrT[DI*DH];
__device__ float d_wxhT[DI*DH], d_wmhT[DI*DH];
__device__ float d_whzT[DH*DH], d_whrT[DH*DH], d_whhT[DH*DH];
__device__ float d_psum[2][DH][NCLU];
__device__ float d_psq [2][DH][NCLU];
__device__ unsigned d_bar[DT];
__device__ unsigned g_count = 0;
__device__ volatile unsigned g_gen = 0;

// ---------------- shared layout (~143KB) ----------------
struct __align__(16) Smem {
    float in4[3*4*DI*NB];      // [c][u][i][b] staged 4 steps
    float ximp[2][DI*NB];      // double-buffered (parity), exchanged
    float xlast[16*NB];
    float xo4[16*NB*4];
    float hdec[DH*NB];         // full, exchanged
    float rh[DH*NB];           // full, exchanged
    float z[DJ*NB];            // z gate; reused as w_hy cache in epilogue
    float gbuf[DJ*NB];         // gamma_h(t+1)
    float h[DJ*HST];
    float hnew[DJ*HST];
    float a[DJ], c[DJ];
    ull   p[TPB*PSTR];         // padded partials
};

// ---------------- helpers ----------------
__device__ __forceinline__ ull pk(float w) {
    ull r; unsigned u = __float_as_uint(w);
    asm("mov.b64 %0, {%1, %1};" : "=l"(r) : "r"(u));
    return r;
}
__device__ __forceinline__ void dfma(ull& d, ull a, ull b) {
    asm("fma.rn.f32x2 %0, %1, %2, %0;" : "+l"(d) : "l"(a), "l"(b));
}
#define ADD2(d, a) asm("add.rn.f32x2 %0, %0, %1;" : "+l"(d) : "l"(a))
// fast sigmoid: MUFU ex2-based exp, fast divide (abs err ~1e-7 at our ranges)
__device__ __forceinline__ float sigf(float x) {
    return __fdividef(1.f, 1.f + __expf(-x));
}
// fast tanh via exp(-2|x|): abs err ~1e-7, no cancellation blowup
__device__ __forceinline__ float tanhf_fast(float x) {
    float ax = fabsf(x);
    float e  = __expf(-2.f * ax);
    float t  = __fdividef(1.f - e, 1.f + e);
    return copysignf(t, x);
}

__device__ __forceinline__ uint32_t s2u(const void* p) {
    uint32_t a;
    asm("{ .reg .u64 t; cvta.to.shared.u64 t, %1; cvt.u32.u64 %0, t; }" : "=r"(a) : "l"(p));
    return a;
}
__device__ __forceinline__ uint32_t mapa_(uint32_t a, uint32_t r) {
    uint32_t o; asm("mapa.shared::cluster.u32 %0, %1, %2;" : "=r"(o) : "r"(a), "r"(r));
    return o;
}
__device__ __forceinline__ void stc1(uint32_t a, float v) {
    asm volatile("st.shared::cluster.b32 [%0], %1;" :: "r"(a), "r"(__float_as_uint(v)) : "memory");
}
__device__ __forceinline__ void stc2(uint32_t a, float2 v) {
    asm volatile("st.shared::cluster.v2.b32 [%0], {%1,%2};" :: "r"(a),
        "r"(__float_as_uint(v.x)), "r"(__float_as_uint(v.y)) : "memory");
}
__device__ __forceinline__ void stc4(uint32_t a, float4 v) {
    asm volatile("st.shared::cluster.v4.b32 [%0], {%1,%2,%3,%4};" :: "r"(a),
        "r"(__float_as_uint(v.x)), "r"(__float_as_uint(v.y)),
        "r"(__float_as_uint(v.z)), "r"(__float_as_uint(v.w)) : "memory");
}
#define CLUSTER_SYNC() do { \
    asm volatile("barrier.cluster.arrive.aligned;" ::: "memory"); \
    asm volatile("barrier.cluster.wait.aligned;"   ::: "memory"); \
} while (0)

// streamed weights [k][cols] float2 stride WS; state v = [k][16b]
template<int WS>
__device__ __forceinline__ void accG(const float2* __restrict__ w, int wcol,
                                     const ulonglong2* __restrict__ v, int bq,
                                     int k0, int k1, ull* A) {
    #pragma unroll 8
    for (int k = k0; k < k1; k++) {
        float2 ww = __ldg(&w[(size_t)k*WS + wcol]);
        ulonglong2 v0 = v[k*4 + bq*2], v1 = v[k*4 + bq*2 + 1];
        ull w0 = pk(ww.x), w1 = pk(ww.y);
        dfma(A[0], w0, v0.x); dfma(A[1], w0, v0.y);
        dfma(A[2], w0, v1.x); dfma(A[3], w0, v1.y);
        dfma(A[4], w1, v0.x); dfma(A[5], w1, v0.y);
        dfma(A[6], w1, v1.x); dfma(A[7], w1, v1.y);
    }
}

__device__ __forceinline__ void stP(Smem* s, int slot, const ull* A) {
    ull* dst = &s->p[(size_t)slot*PSTR];
    #pragma unroll
    for (int q = 0; q < 8; q++) dst[q] = A[q];
}

__device__ __forceinline__ void tpose(const float* __restrict__ src,
                                      float* __restrict__ dst,
                                      int J, int K, int g0, int gs) {
    int n = J * K;
    for (int e = g0; e < n; e += gs) {
        int k = e / J, j = e - k * J;
        dst[e] = src[j * K + k];
    }
}

__device__ __forceinline__ void grid_barrier() {
    __syncthreads();
    if (threadIdx.x == 0) {
        __threadfence();
        unsigned gen = g_gen;
        if (atomicAdd(&g_count, 1u) == (unsigned)(gridDim.x - 1)) {
            g_count = 0u;
            __threadfence();
            g_gen = gen + 1u;
        } else {
            while (g_gen == gen) { __nanosleep(64); }
        }
        __threadfence();
    }
    __syncthreads();
}

__global__ void __cluster_dims__(CSZ,1,1) __launch_bounds__(TPB,1) grud_kernel(
    const float* __restrict__ in,     const float* __restrict__ x_mean,
    const float* __restrict__ w_dg_x, const float* __restrict__ b_dg_x,
    const float* __restrict__ w_dg_h, const float* __restrict__ b_dg_h,
    const float* __restrict__ w_xz,   const float* __restrict__ w_hz,
    const float* __restrict__ w_mz,   const float* __restrict__ b_z,
    const float* __restrict__ w_xr,   const float* __restrict__ w_hr,
    const float* __restrict__ w_mr,   const float* __restrict__ b_r,
    const float* __restrict__ w_xh,   const float* __restrict__ w_hh,
    const float* __restrict__ w_mh,   const float* __restrict__ b_h,
    const float* __restrict__ w_hy,   const float* __restrict__ b_hy,
    const float* __restrict__ bn_g,   const float* __restrict__ bn_b,
    float* __restrict__ out)
{
    extern __shared__ __align__(16) char raw[];
    Smem* s = (Smem*)raw;

    const int tid  = threadIdx.x;
    const int blk  = blockIdx.x;
    const int clu  = blk >> 2;
    const int rank = blk & 3;
    const int b0   = clu * NB;
    const int colbase = rank * DJ;

    float* __restrict__ out_y = out;
    float* __restrict__ out_h = out   + (size_t)DB * DT * DO;
    float* __restrict__ out_x = out_h + (size_t)DB * DT * DH;
    float* __restrict__ out_m = out_x + (size_t)DB * DI * DT;

    // -------- init: transposes, counters, mask copy --------
    {
        int g0 = blk * TPB + tid, gs = NBLK * TPB;
        tpose(w_dg_x, d_wdgxT, DI, DI, g0, gs);
        tpose(w_dg_h, d_wdghT, DH, DI, g0, gs);
        tpose(w_xz,   d_wxzT,  DH, DI, g0, gs);
        tpose(w_mz,   d_wmzT,  DH, DI, g0, gs);
        tpose(w_xr,   d_wxrT,  DH, DI, g0, gs);
        tpose(w_mr,   d_wmrT,  DH, DI, g0, gs);
        tpose(w_xh,   d_wxhT,  DH, DI, g0, gs);
        tpose(w_mh,   d_wmhT,  DH, DI, g0, gs);
        tpose(w_hz,   d_whzT,  DH, DH, g0, gs);
        tpose(w_hr,   d_whrT,  DH, DH, g0, gs);
        tpose(w_hh,   d_whhT,  DH, DH, g0, gs);
        if (blk == 0 && tid < DT) d_bar[tid] = 0u;
        for (int lb = 0; lb < 4; lb++) {
            int b = b0 + rank*4 + lb;
            const float4* src = (const float4*)(in + ((size_t)b*3 + 1) * DI * DT);
            float4* dst = (float4*)(out_m + (size_t)b * DI * DT);
            for (int e = tid; e < DI*DT/4; e += TPB) dst[e] = src[e];
        }
    }
    for (int e = tid; e < DJ*HST; e += TPB) s->h[e] = 0.f;
    for (int e = tid; e < DH*NB; e += TPB) s->hdec[e] = 0.f;
    if (tid < 16*NB) s->xlast[tid] = 0.f;

    grid_barrier();   // weights + counters visible

    const float* PF = (const float*)s->p;

    // -------- prologue: stage steps 0..3, Phase A for t=0 --------
    {
        for (int e = tid; e < 3*DI*NB; e += TPB) {
            int cc = e >> 10, r = e & 1023;
            int i = r >> 4, b = r & 15;
            float4 v = *(const float4*)&in[(((size_t)(b0+b)*3 + cc)*DI + i)*DT + 0];
            s->in4[((cc*4+0)*DI + i)*NB + b] = v.x;
            s->in4[((cc*4+1)*DI + i)*NB + b] = v.y;
            s->in4[((cc*4+2)*DI + i)*NB + b] = v.z;
            s->in4[((cc*4+3)*DI + i)*NB + b] = v.w;
        }
        __syncthreads();
        const ulonglong2* DD = (const ulonglong2*)&s->in4[(2*4+0)*DI*NB];
        if (tid < 256) {
            int jp = tid & 31, bq = (tid>>5)&1, ks = tid>>6;
            ull A[8] = {0,0,0,0,0,0,0,0};
            accG<128>((const float2*)d_wdghT, rank*32 + jp, DD, bq, ks*16, ks*16+16, A);
            stP(s, tid, A);
        } else if (tid < 384) {
            int idx = tid - 256;
            int ip = idx & 7, bq = (idx>>3)&1, ks = idx>>4;
            ull A[8] = {0,0,0,0,0,0,0,0};
            accG<32>((const float2*)d_wdgxT, rank*8 + ip, DD, bq, ks*8, ks*8+8, A);
            stP(s, tid, A);
        }
        __syncthreads();
        const float* Xc = &s->in4[(0*4+0)*DI*NB];
        const float* Mc = &s->in4[(1*4+0)*DI*NB];
        #pragma unroll
        for (int hf = 0; hf < 2; hf++) {
            int idx = hf*TPB + tid;
            int b = idx & 15, j = idx >> 4;
            int jp = j >> 1, lo = j & 1, bq = b >> 3, bo = b & 7;
            float f = 0.f;
            #pragma unroll
            for (int ks = 0; ks < 4; ks++) f += PF[(ks*64 + bq*32 + jp)*PSF + lo*8 + bo];
            s->gbuf[j*NB + b] = __expf(-fmaxf(f + b_dg_h[colbase + j], 0.f));
        }
        if (tid < 256) {
            int il = tid >> 4, b = tid & 15;
            int ip = il >> 1, lo = il & 1, bq = b >> 3, bo = b & 7;
            int ig = rank*16 + il;
            float f = 0.f;
            #pragma unroll
            for (int ks = 0; ks < 8; ks++) f += PF[(256 + ks*16 + bq*8 + ip)*PSF + lo*8 + bo];
            float gg = __expf(-fmaxf(f + b_dg_x[ig], 0.f));
            float mm = Mc[ig*NB + b], xx = Xc[ig*NB + b];
            float xl = (mm > 0.f) ? xx : s->xlast[il*NB + b];
            s->xlast[il*NB + b] = xl;
            float xv = mm*xx + (1.f-mm)*(gg*xl + (1.f-gg)*x_mean[ig]);
            s->ximp[0][ig*NB + b] = xv;
            uint32_t la = s2u(&s->ximp[0][ig*NB + b]);
            #pragma unroll
            for (int r = 0; r < CSZ; r++)
                if (r != rank) stc1(mapa_(la, (uint32_t)r), xv);
            s->xo4[(il*NB + b)*4 + 0] = xv;
        }
        CLUSTER_SYNC();
    }

    for (int t = 0; t < DT; t++) {
        const int u = t & 3;
        const ulonglong2* XI = (const ulonglong2*)s->ximp[t & 1];
        const ulonglong2* HD = (const ulonglong2*)s->hdec;
        const ulonglong2* RH = (const ulonglong2*)s->rh;
        const ulonglong2* MM = (const ulonglong2*)&s->in4[(1*4+u)*DI*NB];

        // ---- Phase B matmul: z (0..255) / r (256..511) ----
        {
            int g = tid >> 8, ks = (tid>>6)&3, bq = (tid>>5)&1, jp = tid & 31;
            const float2* wx = (const float2*)(g ? d_wxrT : d_wxzT);
            const float2* wm = (const float2*)(g ? d_wmrT : d_wmzT);
            const float2* wh = (const float2*)(g ? d_whrT : d_whzT);
            int wc = rank*32 + jp;
            ull A[8] = {0,0,0,0,0,0,0,0};
            switch (ks) {
                case 0: accG<128>(wx, wc, XI, bq, 0, 64, A);
                        accG<128>(wm, wc, MM, bq, 0, 32, A); break;
                case 1: accG<128>(wm, wc, MM, bq, 32, 64, A);
                        accG<128>(wh, wc, HD, bq, 0, 64, A); break;
                case 2: accG<128>(wh, wc, HD, bq, 64, 160, A); break;
                default: accG<128>(wh, wc, HD, bq, 160, 256, A); break;
            }
            stP(s, tid, A);
        }
        __syncthreads();

        // ---- Phase B combine: 512 threads x 4 values (g, j, batch-quad) ----
        {
            int g = tid >> 8, idx = tid & 255;
            int j = idx >> 2, q4 = idx & 3;
            int jp = j >> 1, lo = j & 1, jg = colbase + j;
            int bq = q4 >> 1;
            const ull* P = s->p;
            int base = (g*256 + bq*32 + jp)*PSTR + lo*4 + (q4 & 1)*2;
            ull U0 = P[base], U1 = P[base+1];
            #pragma unroll
            for (int ks = 1; ks < 4; ks++) {
                int o2 = base + ks*64*PSTR;
                ADD2(U0, P[o2]); ADD2(U1, P[o2+1]);
            }
            float f[4];
            ((ull*)f)[0] = U0; ((ull*)f)[1] = U1;
            if (g == 0) {
                float bzv = b_z[jg];
                float4 z0; float* zp = (float*)&z0;
                #pragma unroll
                for (int q = 0; q < 4; q++) zp[q] = sigf(f[q] + bzv);
                *(float4*)&s->z[j*NB + q4*4] = z0;
            } else {
                float brv = b_r[jg];
                float4 r0; float* rp = (float*)&r0;
                #pragma unroll
                for (int q = 0; q < 4; q++)
                    rp[q] = sigf(f[q] + brv) * s->hdec[jg*NB + q4*4 + q];
                *(float4*)&s->rh[jg*NB + q4*4] = r0;
                uint32_t la = s2u(&s->rh[jg*NB + q4*4]);
                #pragma unroll
                for (int r = 0; r < CSZ; r++)
                    if (r != rank) stc4(mapa_(la, (uint32_t)r), r0);
            }
        }
        CLUSTER_SYNC();   // rh full everywhere

        // ---- Phase C matmul: h_tilde preact, 8 k-splits of 48 ----
        {
            int ks = tid >> 6, bq = (tid>>5)&1, jp = tid & 31;
            const float2* wxh2 = (const float2*)d_wxhT;
            const float2* wmh2 = (const float2*)d_wmhT;
            const float2* whh2 = (const float2*)d_whhT;
            int wc = rank*32 + jp;
            ull A[8] = {0,0,0,0,0,0,0,0};
            switch (ks) {
                case 0: accG<128>(wxh2, wc, XI, bq, 0, 48, A); break;
                case 1: accG<128>(wxh2, wc, XI, bq, 48, 64, A);
                        accG<128>(wmh2, wc, MM, bq, 0, 32, A); break;
                case 2: accG<128>(wmh2, wc, MM, bq, 32, 64, A);
                        accG<128>(whh2, wc, RH, bq, 0, 16, A); break;
                case 3: accG<128>(whh2, wc, RH, bq, 16, 64, A); break;
                case 4: accG<128>(whh2, wc, RH, bq, 64, 112, A); break;
                case 5: accG<128>(whh2, wc, RH, bq, 112, 160, A); break;
                case 6: accG<128>(whh2, wc, RH, bq, 160, 208, A); break;
                default: accG<128>(whh2, wc, RH, bq, 208, 256, A); break;
            }
            stP(s, tid, A);
        }
        __syncthreads();

        // ---- Phase C combine: 256 threads x 4 values + restage in4 ----
        if (tid < 256) {
            int j = tid >> 2, q4 = tid & 3;
            int jp = j >> 1, lo = j & 1, jg = colbase + j;
            int bq = q4 >> 1;
            const ull* P = s->p;
            int base = (bq*32 + jp)*PSTR + lo*4 + (q4 & 1)*2;
            ull U0 = P[base], U1 = P[base+1];
            #pragma unroll
            for (int ks = 1; ks < 8; ks++) {
                int o2 = base + ks*64*PSTR;
                ADD2(U0, P[o2]); ADD2(U1, P[o2+1]);
            }
            float f[4];
            ((ull*)f)[0] = U0; ((ull*)f)[1] = U1;
            float bh = b_h[jg];
            float ps = 0.f, pq = 0.f;
            #pragma unroll
            for (int q = 0; q < 4; q++) {
                int b = q4*4 + q;
                float ht = tanhf_fast(f[q] + bh);
                float zz = s->z[j*NB + b], hd = s->hdec[jg*NB + b];
                float h1 = (1.f - zz)*hd + zz*ht;
                s->hnew[j*HST + b] = h1;
                ps += h1; pq += h1*h1;
            }
            ps += __shfl_xor_sync(0xffffffffu, ps, 1);
            ps += __shfl_xor_sync(0xffffffffu, ps, 2);
            pq += __shfl_xor_sync(0xffffffffu, pq, 1);
            pq += __shfl_xor_sync(0xffffffffu, pq, 2);
            if (q4 == 0) {
                int buf = t & 1;
                d_psum[buf][jg][clu] = ps;
                d_psq [buf][jg][clu] = pq;
            }
        }
        if ((t+1) < DT && (((t+1) & 3) == 0)) {
            for (int e = tid; e < 3*DI*NB; e += TPB) {
                int cc = e >> 10, r = e & 1023;
                int i = r >> 4, b = r & 15;
                float4 v = *(const float4*)&in[(((size_t)(b0+b)*3 + cc)*DI + i)*DT + (t+1)];
                s->in4[((cc*4+0)*DI + i)*NB + b] = v.x;
                s->in4[((cc*4+1)*DI + i)*NB + b] = v.y;
                s->in4[((cc*4+2)*DI + i)*NB + b] = v.z;
                s->in4[((cc*4+3)*DI + i)*NB + b] = v.w;
            }
        }
        __syncthreads();

        // ---- arrive at grid barrier, then Phase A(t+1) in its shadow ----
        if (tid == 0) { __threadfence(); atomicAdd(&d_bar[t], 1u); }

        if ((t+1) < DT) {
            const int u1 = (t+1) & 3;
            const ulonglong2* DD = (const ulonglong2*)&s->in4[(2*4+u1)*DI*NB];
            if (tid < 256) {
                int jp = tid & 31, bq = (tid>>5)&1, ks = tid>>6;
                ull A[8] = {0,0,0,0,0,0,0,0};
                accG<128>((const float2*)d_wdghT, rank*32 + jp, DD, bq, ks*16, ks*16+16, A);
                stP(s, tid, A);
            } else if (tid < 384) {
                int idx = tid - 256;
                int ip = idx & 7, bq = (idx>>3)&1, ks = idx>>4;
                ull A[8] = {0,0,0,0,0,0,0,0};
                accG<32>((const float2*)d_wdgxT, rank*8 + ip, DD, bq, ks*8, ks*8+8, A);
                stP(s, tid, A);
            }
        }
        __syncthreads();
        if ((t+1) < DT) {
            const int u1 = (t+1) & 3;
            const int par = (t+1) & 1;
            const float* Xc = &s->in4[(0*4+u1)*DI*NB];
            const float* Mc = &s->in4[(1*4+u1)*DI*NB];
            #pragma unroll
            for (int hf = 0; hf < 2; hf++) {
                int idx = hf*TPB + tid;
                int b = idx & 15, j = idx >> 4;
                int jp = j >> 1, lo = j & 1, bq = b >> 3, bo = b & 7;
                float f = 0.f;
                #pragma unroll
                for (int ks = 0; ks < 4; ks++)
                    f += PF[(ks*64 + bq*32 + jp)*PSF + lo*8 + bo];
                s->gbuf[j*NB + b] = __expf(-fmaxf(f + b_dg_h[colbase + j], 0.f));
            }
            if (tid < 256) {
                int il = tid >> 4, b = tid & 15;
                int ip = il >> 1, lo = il & 1, bq = b >> 3, bo = b & 7;
                int ig = rank*16 + il;
                float f = 0.f;
                #pragma unroll
                for (int ks = 0; ks < 8; ks++)
                    f += PF[(256 + ks*16 + bq*8 + ip)*PSF + lo*8 + bo];
                float gg = __expf(-fmaxf(f + b_dg_x[ig], 0.f));
                float mm = Mc[ig*NB + b], xx = Xc[ig*NB + b];
                float xl = (mm > 0.f) ? xx : s->xlast[il*NB + b];
                s->xlast[il*NB + b] = xl;
                float xv = mm*xx + (1.f-mm)*(gg*xl + (1.f-gg)*x_mean[ig]);
                s->ximp[par][ig*NB + b] = xv;
                uint32_t la = s2u(&s->ximp[par][ig*NB + b]);
                #pragma unroll
                for (int r = 0; r < CSZ; r++)
                    if (r != rank) stc1(mapa_(la, (uint32_t)r), xv);
                s->xo4[(il*NB + b)*4 + u1] = xv;
                if (u1 == 3)
                    *(float4*)&out_x[((size_t)(b0+b)*DI + ig)*DT + (t+1) - 3] =
                        *(const float4*)&s->xo4[(il*NB + b)*4];
            }
        }
        __syncthreads();

        // ---- wait for all CTAs ----
        if (tid == 0) {
            while (*(volatile unsigned*)&d_bar[t] < (unsigned)NBLK) { __nanosleep(32); }
            __threadfence();
        }
        __syncthreads();

        // ---- Phase D: BN stats (256 threads: j x quarter, 2-level shfl) ----
        if (tid < 256) {
            int j = tid >> 2, qu = tid & 3;
            int jg = colbase + j, buf = t & 1;
            const float4* ps = (const float4*)d_psum[buf][jg] + qu*2;
            const float4* pq = (const float4*)d_psq [buf][jg] + qu*2;
            float s1 = 0.f, s2 = 0.f;
            #pragma unroll
            for (int pp = 0; pp < 2; pp++) {
                float4 a4 = __ldcg(ps + pp);
                float4 c4 = __ldcg(pq + pp);
                s1 += (a4.x + a4.y) + (a4.z + a4.w);
                s2 += (c4.x + c4.y) + (c4.z + c4.w);
            }
            s1 += __shfl_xor_sync(0xffffffffu, s1, 1);
            s1 += __shfl_xor_sync(0xffffffffu, s1, 2);
            s2 += __shfl_xor_sync(0xffffffffu, s2, 1);
            s2 += __shfl_xor_sync(0xffffffffu, s2, 2);
            if (qu == 0) {
                float mu  = s1 * (1.f/(float)DB);
                float var = fmaf(s2, 1.f/(float)DB, -mu*mu);
                float rs  = rsqrtf(var + 1e-5f);
                float aa  = rs * bn_g[jg];
                s->a[j] = aa;
                s->c[j] = fmaf(-mu, aa, bn_b[jg]);
            }
        }
        __syncthreads();

        // ---- Phase E: 512 threads x 2: normalize, carry h, out_h, hdec ----
        {
            int j = tid & 63, grp = tid >> 6;   // grp 0..7 -> batch pair
            int jg = colbase + j;
            float aa = s->a[j], cc = s->c[j];
            float2 hd2; float* hp = (float*)&hd2;
            #pragma unroll
            for (int u2 = 0; u2 < 2; u2++) {
                int b = grp*2 + u2;
                float hb = fmaf(s->hnew[j*HST + b], aa, cc);
                s->h[j*HST + b] = hb;
                out_h[((size_t)(b0+b)*DT + t)*DH + jg] = hb;
                hp[u2] = s->gbuf[j*NB + b] * hb;
            }
            *(float2*)&s->hdec[jg*NB + grp*2] = hd2;
            uint32_t la = s2u(&s->hdec[jg*NB + grp*2]);
            #pragma unroll
            for (int r = 0; r < CSZ; r++)
                if (r != rank) stc2(mapa_(la, (uint32_t)r), hd2);
        }
        CLUSTER_SYNC();   // hdec + ximp exchanges complete (full block barrier)
    }

    // -------- epilogue: y = sigmoid(h @ w_hy^T + b) from out_h --------
    __threadfence();
    CLUSTER_SYNC();          // peers' out_h STG visible
    {
        float* swhy = s->z;  // 512-float cache
        if (tid < DO*DH) swhy[tid] = w_hy[tid];
        __syncthreads();
        float bhy0 = b_hy[0], bhy1 = b_hy[1];
        int w = tid >> 5, lane = tid & 31;
        for (int task = w; task < 4*DT*DO; task += 16) {
            int t = task >> 3, sub = task & 7;
            int lb = sub >> 1, o = sub & 1;
            int b = b0 + rank*4 + lb;
            const float* hrow = out_h + ((size_t)b*DT + t)*DH;
            float acc = 0.f;
            #pragma unroll
            for (int kk = 0; kk < 8; kk++)
                acc = fmaf(__ldcg(&hrow[lane + kk*32]), swhy[o*DH + lane + kk*32], acc);
            #pragma unroll
            for (int off = 16; off; off >>= 1)
                acc += __shfl_xor_sync(0xffffffffu, acc, off);
            if (lane == 0)
                out_y[((size_t)b*DT + t)*DO + o] =
                    1.f / (1.f + expf(-(acc + (o ? bhy1 : bhy0))));
        }
    }
}

extern "C" void kernel_launch(void* const* d_in, const int* in_sizes, int n_in,
                              void* d_out, int out_size) {
    cudaFuncSetAttribute(grud_kernel, cudaFuncAttributeMaxDynamicSharedMemorySize,
                         (int)sizeof(Smem));
    grud_kernel<<<NBLK, TPB, sizeof(Smem)>>>(
        (const float*)d_in[0],  (const float*)d_in[1],
        (const float*)d_in[2],  (const float*)d_in[3],
        (const float*)d_in[4],  (const float*)d_in[5],
        (const float*)d_in[6],  (const float*)d_in[7],
        (const float*)d_in[8],  (const float*)d_in[9],
        (const float*)d_in[10], (const float*)d_in[11],
        (const float*)d_in[12], (const float*)d_in[13],
        (const float*)d_in[14], (const float*)d_in[15],
        (const float*)d_in[16], (const float*)d_in[17],
        (const float*)d_in[18], (const float*)d_in[19],
        (const float*)d_in[20], (const float*)d_in[21],
        (float*)d_out);
}

// round 17
// speedup vs baseline: 1.0473x; 1.0473x over previous
#include <cuda_runtime.h>
#include <math.h>
#include <stdint.h>

typedef unsigned long long ull;

#define TPB  512
#define NBLK 128
#define CSZ  4
#define NCLU 32
#define DB 512
#define DI 64
#define DH 256
#define DJ 64     /* j cols per CTA */
#define NB 16     /* batches per cluster */
#define DO 2
#define DT 200
#define HST 17    /* padded stride for h / hnew */
#define PSTR 9    /* ull stride per partial slot (bank-conflict pad) */
#define PSF 18    /* float stride per slot */

// ---------------- static device scratch ----------------
__device__ float d_wdgxT[DI*DI];
__device__ float d_wdghT[DI*DH];
__device__ float d_wxzT[DI*DH], d_wmzT[DI*DH];
__device__ float d_wxrT[DI*DH], d_wmrT[DI*DH];
__device__ float d_wxhT[DI*DH], d_wmhT[DI*DH];
__device__ float d_whzT[DH*DH], d_whrT[DH*DH], d_whhT[DH*DH];
__device__ float d_psum[2][DH][NCLU];
__device__ float d_psq [2][DH][NCLU];
__device__ unsigned d_bar[DT];
__device__ unsigned g_count = 0;
__device__ volatile unsigned g_gen = 0;

// ---------------- shared layout (~143KB) ----------------
struct __align__(16) Smem {
    float in4[3*4*DI*NB];      // [c][u][i][b] staged 4 steps
    float ximp[2][DI*NB];      // double-buffered (parity), exchanged
    float xlast[16*NB];
    float xo4[16*NB*4];
    float hdec[DH*NB];         // full, exchanged
    float rh[DH*NB];           // full, exchanged
    float z[DJ*NB];            // z gate; reused as w_hy cache in epilogue
    float gbuf[DJ*NB];         // gamma_h(t+1)
    float h[DJ*HST];
    float hnew[DJ*HST];
    float a[DJ], c[DJ];
    ull   p[TPB*PSTR];         // padded partials
};

// ---------------- helpers ----------------
__device__ __forceinline__ ull pk(float w) {
    ull r; unsigned u = __float_as_uint(w);
    asm("mov.b64 %0, {%1, %1};" : "=l"(r) : "r"(u));
    return r;
}
__device__ __forceinline__ void dfma(ull& d, ull a, ull b) {
    asm("fma.rn.f32x2 %0, %1, %2, %0;" : "+l"(d) : "l"(a), "l"(b));
}
#define ADD2(d, a) asm("add.rn.f32x2 %0, %0, %1;" : "+l"(d) : "l"(a))
// fast sigmoid: MUFU ex2-based exp + fast reciprocal (abs err ~1e-7)
__device__ __forceinline__ float sigf(float x) {
    return __fdividef(1.f, 1.f + __expf(-x));
}
// fast tanh via exp(-2|x|): abs err ~1e-7, no cancellation blowup
__device__ __forceinline__ float tanhf_fast(float x) {
    float ax = fabsf(x);
    float e  = __expf(-2.f * ax);
    float t  = __fdividef(1.f - e, 1.f + e);
    return copysignf(t, x);
}

__device__ __forceinline__ uint32_t s2u(const void* p) {
    uint32_t a;
    asm("{ .reg .u64 t; cvta.to.shared.u64 t, %1; cvt.u32.u64 %0, t; }" : "=r"(a) : "l"(p));
    return a;
}
__device__ __forceinline__ uint32_t mapa_(uint32_t a, uint32_t r) {
    uint32_t o; asm("mapa.shared::cluster.u32 %0, %1, %2;" : "=r"(o) : "r"(a), "r"(r));
    return o;
}
__device__ __forceinline__ void stc1(uint32_t a, float v) {
    asm volatile("st.shared::cluster.b32 [%0], %1;" :: "r"(a), "r"(__float_as_uint(v)) : "memory");
}
__device__ __forceinline__ void stc4(uint32_t a, float4 v) {
    asm volatile("st.shared::cluster.v4.b32 [%0], {%1,%2,%3,%4};" :: "r"(a),
        "r"(__float_as_uint(v.x)), "r"(__float_as_uint(v.y)),
        "r"(__float_as_uint(v.z)), "r"(__float_as_uint(v.w)) : "memory");
}
#define CLUSTER_SYNC() do { \
    asm volatile("barrier.cluster.arrive.aligned;" ::: "memory"); \
    asm volatile("barrier.cluster.wait.aligned;"   ::: "memory"); \
} while (0)

// streamed weights [k][cols] float2 stride WS; state v = [k][16b]
template<int WS>
__device__ __forceinline__ void accG(const float2* __restrict__ w, int wcol,
                                     const ulonglong2* __restrict__ v, int bq,
                                     int k0, int k1, ull* A) {
    #pragma unroll 8
    for (int k = k0; k < k1; k++) {
        float2 ww = __ldg(&w[(size_t)k*WS + wcol]);
        ulonglong2 v0 = v[k*4 + bq*2], v1 = v[k*4 + bq*2 + 1];
        ull w0 = pk(ww.x), w1 = pk(ww.y);
        dfma(A[0], w0, v0.x); dfma(A[1], w0, v0.y);
        dfma(A[2], w0, v1.x); dfma(A[3], w0, v1.y);
        dfma(A[4], w1, v0.x); dfma(A[5], w1, v0.y);
        dfma(A[6], w1, v1.x); dfma(A[7], w1, v1.y);
    }
}

__device__ __forceinline__ void stP(Smem* s, int slot, const ull* A) {
    ull* dst = &s->p[(size_t)slot*PSTR];
    #pragma unroll
    for (int q = 0; q < 8; q++) dst[q] = A[q];
}

__device__ __forceinline__ void tpose(const float* __restrict__ src,
                                      float* __restrict__ dst,
                                      int J, int K, int g0, int gs) {
    int n = J * K;
    for (int e = g0; e < n; e += gs) {
        int k = e / J, j = e - k * J;
        dst[e] = src[j * K + k];
    }
}

__device__ __forceinline__ void grid_barrier() {
    __syncthreads();
    if (threadIdx.x == 0) {
        __threadfence();
        unsigned gen = g_gen;
        if (atomicAdd(&g_count, 1u) == (unsigned)(gridDim.x - 1)) {
            g_count = 0u;
            __threadfence();
            g_gen = gen + 1u;
        } else {
            while (g_gen == gen) { __nanosleep(64); }
        }
        __threadfence();
    }
    __syncthreads();
}

__global__ void __cluster_dims__(CSZ,1,1) __launch_bounds__(TPB,1) grud_kernel(
    const float* __restrict__ in,     const float* __restrict__ x_mean,
    const float* __restrict__ w_dg_x, const float* __restrict__ b_dg_x,
    const float* __restrict__ w_dg_h, const float* __restrict__ b_dg_h,
    const float* __restrict__ w_xz,   const float* __restrict__ w_hz,
    const float* __restrict__ w_mz,   const float* __restrict__ b_z,
    const float* __restrict__ w_xr,   const float* __restrict__ w_hr,
    const float* __restrict__ w_mr,   const float* __restrict__ b_r,
    const float* __restrict__ w_xh,   const float* __restrict__ w_hh,
    const float* __restrict__ w_mh,   const float* __restrict__ b_h,
    const float* __restrict__ w_hy,   const float* __restrict__ b_hy,
    const float* __restrict__ bn_g,   const float* __restrict__ bn_b,
    float* __restrict__ out)
{
    extern __shared__ __align__(16) char raw[];
    Smem* s = (Smem*)raw;

    const int tid  = threadIdx.x;
    const int blk  = blockIdx.x;
    const int clu  = blk >> 2;
    const int rank = blk & 3;
    const int b0   = clu * NB;
    const int colbase = rank * DJ;

    float* __restrict__ out_y = out;
    float* __restrict__ out_h = out   + (size_t)DB * DT * DO;
    float* __restrict__ out_x = out_h + (size_t)DB * DT * DH;
    float* __restrict__ out_m = out_x + (size_t)DB * DI * DT;

    // -------- init: transposes, counters, mask copy --------
    {
        int g0 = blk * TPB + tid, gs = NBLK * TPB;
        tpose(w_dg_x, d_wdgxT, DI, DI, g0, gs);
        tpose(w_dg_h, d_wdghT, DH, DI, g0, gs);
        tpose(w_xz,   d_wxzT,  DH, DI, g0, gs);
        tpose(w_mz,   d_wmzT,  DH, DI, g0, gs);
        tpose(w_xr,   d_wxrT,  DH, DI, g0, gs);
        tpose(w_mr,   d_wmrT,  DH, DI, g0, gs);
        tpose(w_xh,   d_wxhT,  DH, DI, g0, gs);
        tpose(w_mh,   d_wmhT,  DH, DI, g0, gs);
        tpose(w_hz,   d_whzT,  DH, DH, g0, gs);
        tpose(w_hr,   d_whrT,  DH, DH, g0, gs);
        tpose(w_hh,   d_whhT,  DH, DH, g0, gs);
        if (blk == 0 && tid < DT) d_bar[tid] = 0u;
        for (int lb = 0; lb < 4; lb++) {
            int b = b0 + rank*4 + lb;
            const float4* src = (const float4*)(in + ((size_t)b*3 + 1) * DI * DT);
            float4* dst = (float4*)(out_m + (size_t)b * DI * DT);
            for (int e = tid; e < DI*DT/4; e += TPB) dst[e] = src[e];
        }
    }
    for (int e = tid; e < DJ*HST; e += TPB) s->h[e] = 0.f;
    for (int e = tid; e < DH*NB; e += TPB) s->hdec[e] = 0.f;
    if (tid < 16*NB) s->xlast[tid] = 0.f;

    grid_barrier();   // weights + counters visible

    const float* PF = (const float*)s->p;

    // -------- prologue: stage steps 0..3, Phase A for t=0 --------
    {
        for (int e = tid; e < 3*DI*NB; e += TPB) {
            int cc = e >> 10, r = e & 1023;
            int i = r >> 4, b = r & 15;
            float4 v = *(const float4*)&in[(((size_t)(b0+b)*3 + cc)*DI + i)*DT + 0];
            s->in4[((cc*4+0)*DI + i)*NB + b] = v.x;
            s->in4[((cc*4+1)*DI + i)*NB + b] = v.y;
            s->in4[((cc*4+2)*DI + i)*NB + b] = v.z;
            s->in4[((cc*4+3)*DI + i)*NB + b] = v.w;
        }
        __syncthreads();
        const ulonglong2* DD = (const ulonglong2*)&s->in4[(2*4+0)*DI*NB];
        if (tid < 256) {
            int jp = tid & 31, bq = (tid>>5)&1, ks = tid>>6;
            ull A[8] = {0,0,0,0,0,0,0,0};
            accG<128>((const float2*)d_wdghT, rank*32 + jp, DD, bq, ks*16, ks*16+16, A);
            stP(s, tid, A);
        } else if (tid < 384) {
            int idx = tid - 256;
            int ip = idx & 7, bq = (idx>>3)&1, ks = idx>>4;
            ull A[8] = {0,0,0,0,0,0,0,0};
            accG<32>((const float2*)d_wdgxT, rank*8 + ip, DD, bq, ks*8, ks*8+8, A);
            stP(s, tid, A);
        }
        __syncthreads();
        const float* Xc = &s->in4[(0*4+0)*DI*NB];
        const float* Mc = &s->in4[(1*4+0)*DI*NB];
        #pragma unroll
        for (int hf = 0; hf < 2; hf++) {
            int idx = hf*TPB + tid;
            int b = idx & 15, j = idx >> 4;
            int jp = j >> 1, lo = j & 1, bq = b >> 3, bo = b & 7;
            float f = 0.f;
            #pragma unroll
            for (int ks = 0; ks < 4; ks++) f += PF[(ks*64 + bq*32 + jp)*PSF + lo*8 + bo];
            s->gbuf[j*NB + b] = __expf(-fmaxf(f + b_dg_h[colbase + j], 0.f));
        }
        if (tid < 256) {
            int il = tid >> 4, b = tid & 15;
            int ip = il >> 1, lo = il & 1, bq = b >> 3, bo = b & 7;
            int ig = rank*16 + il;
            float f = 0.f;
            #pragma unroll
            for (int ks = 0; ks < 8; ks++) f += PF[(256 + ks*16 + bq*8 + ip)*PSF + lo*8 + bo];
            float gg = __expf(-fmaxf(f + b_dg_x[ig], 0.f));
            float mm = Mc[ig*NB + b], xx = Xc[ig*NB + b];
            float xl = (mm > 0.f) ? xx : s->xlast[il*NB + b];
            s->xlast[il*NB + b] = xl;
            float xv = mm*xx + (1.f-mm)*(gg*xl + (1.f-gg)*x_mean[ig]);
            s->ximp[0][ig*NB + b] = xv;
            uint32_t la = s2u(&s->ximp[0][ig*NB + b]);
            #pragma unroll
            for (int r = 0; r < CSZ; r++)
                if (r != rank) stc1(mapa_(la, (uint32_t)r), xv);
            s->xo4[(il*NB + b)*4 + 0] = xv;
        }
        CLUSTER_SYNC();
    }

    for (int t = 0; t < DT; t++) {
        const int u = t & 3;
        const ulonglong2* XI = (const ulonglong2*)s->ximp[t & 1];
        const ulonglong2* HD = (const ulonglong2*)s->hdec;
        const ulonglong2* RH = (const ulonglong2*)s->rh;
        const ulonglong2* MM = (const ulonglong2*)&s->in4[(1*4+u)*DI*NB];

        // ---- Phase B matmul: z (0..255) / r (256..511) ----
        {
            int g = tid >> 8, ks = (tid>>6)&3, bq = (tid>>5)&1, jp = tid & 31;
            const float2* wx = (const float2*)(g ? d_wxrT : d_wxzT);
            const float2* wm = (const float2*)(g ? d_wmrT : d_wmzT);
            const float2* wh = (const float2*)(g ? d_whrT : d_whzT);
            int wc = rank*32 + jp;
            ull A[8] = {0,0,0,0,0,0,0,0};
            switch (ks) {
                case 0: accG<128>(wx, wc, XI, bq, 0, 64, A);
                        accG<128>(wm, wc, MM, bq, 0, 32, A); break;
                case 1: accG<128>(wm, wc, MM, bq, 32, 64, A);
                        accG<128>(wh, wc, HD, bq, 0, 64, A); break;
                case 2: accG<128>(wh, wc, HD, bq, 64, 160, A); break;
                default: accG<128>(wh, wc, HD, bq, 160, 256, A); break;
            }
            stP(s, tid, A);
        }
        __syncthreads();

        // ---- Phase B combine: 512 threads x 4 values (g, j, batch-quad) ----
        {
            int g = tid >> 8, idx = tid & 255;
            int j = idx >> 2, q4 = idx & 3;
            int jp = j >> 1, lo = j & 1, jg = colbase + j;
            int bq = q4 >> 1;
            const ull* P = s->p;
            int base = (g*256 + bq*32 + jp)*PSTR + lo*4 + (q4 & 1)*2;
            ull U0 = P[base], U1 = P[base+1];
            #pragma unroll
            for (int ks = 1; ks < 4; ks++) {
                int o2 = base + ks*64*PSTR;
                ADD2(U0, P[o2]); ADD2(U1, P[o2+1]);
            }
            float f[4];
            ((ull*)f)[0] = U0; ((ull*)f)[1] = U1;
            if (g == 0) {
                float bzv = b_z[jg];
                float4 z0; float* zp = (float*)&z0;
                #pragma unroll
                for (int q = 0; q < 4; q++) zp[q] = sigf(f[q] + bzv);
                *(float4*)&s->z[j*NB + q4*4] = z0;
            } else {
                float brv = b_r[jg];
                float4 r0; float* rp = (float*)&r0;
                #pragma unroll
                for (int q = 0; q < 4; q++)
                    rp[q] = sigf(f[q] + brv) * s->hdec[jg*NB + q4*4 + q];
                *(float4*)&s->rh[jg*NB + q4*4] = r0;
                uint32_t la = s2u(&s->rh[jg*NB + q4*4]);
                #pragma unroll
                for (int r = 0; r < CSZ; r++)
                    if (r != rank) stc4(mapa_(la, (uint32_t)r), r0);
            }
        }
        CLUSTER_SYNC();   // rh full everywhere

        // ---- Phase C matmul: h_tilde preact, 8 k-splits of 48 ----
        {
            int ks = tid >> 6, bq = (tid>>5)&1, jp = tid & 31;
            const float2* wxh2 = (const float2*)d_wxhT;
            const float2* wmh2 = (const float2*)d_wmhT;
            const float2* whh2 = (const float2*)d_whhT;
            int wc = rank*32 + jp;
            ull A[8] = {0,0,0,0,0,0,0,0};
            switch (ks) {
                case 0: accG<128>(wxh2, wc, XI, bq, 0, 48, A); break;
                case 1: accG<128>(wxh2, wc, XI, bq, 48, 64, A);
                        accG<128>(wmh2, wc, MM, bq, 0, 32, A); break;
                case 2: accG<128>(wmh2, wc, MM, bq, 32, 64, A);
                        accG<128>(whh2, wc, RH, bq, 0, 16, A); break;
                case 3: accG<128>(whh2, wc, RH, bq, 16, 64, A); break;
                case 4: accG<128>(whh2, wc, RH, bq, 64, 112, A); break;
                case 5: accG<128>(whh2, wc, RH, bq, 112, 160, A); break;
                case 6: accG<128>(whh2, wc, RH, bq, 160, 208, A); break;
                default: accG<128>(whh2, wc, RH, bq, 208, 256, A); break;
            }
            stP(s, tid, A);
        }
        __syncthreads();

        // ---- Phase C combine: 256 threads x 4 values + restage in4 ----
        if (tid < 256) {
            int j = tid >> 2, q4 = tid & 3;
            int jp = j >> 1, lo = j & 1, jg = colbase + j;
            int bq = q4 >> 1;
            const ull* P = s->p;
            int base = (bq*32 + jp)*PSTR + lo*4 + (q4 & 1)*2;
            ull U0 = P[base], U1 = P[base+1];
            #pragma unroll
            for (int ks = 1; ks < 8; ks++) {
                int o2 = base + ks*64*PSTR;
                ADD2(U0, P[o2]); ADD2(U1, P[o2+1]);
            }
            float f[4];
            ((ull*)f)[0] = U0; ((ull*)f)[1] = U1;
            float bh = b_h[jg];
            float ps = 0.f, pq = 0.f;
            #pragma unroll
            for (int q = 0; q < 4; q++) {
                int b = q4*4 + q;
                float ht = tanhf_fast(f[q] + bh);
                float zz = s->z[j*NB + b], hd = s->hdec[jg*NB + b];
                float h1 = (1.f - zz)*hd + zz*ht;
                s->hnew[j*HST + b] = h1;
                ps += h1; pq += h1*h1;
            }
            ps += __shfl_xor_sync(0xffffffffu, ps, 1);
            ps += __shfl_xor_sync(0xffffffffu, ps, 2);
            pq += __shfl_xor_sync(0xffffffffu, pq, 1);
            pq += __shfl_xor_sync(0xffffffffu, pq, 2);
            if (q4 == 0) {
                int buf = t & 1;
                d_psum[buf][jg][clu] = ps;
                d_psq [buf][jg][clu] = pq;
            }
        }
        if ((t+1) < DT && (((t+1) & 3) == 0)) {
            for (int e = tid; e < 3*DI*NB; e += TPB) {
                int cc = e >> 10, r = e & 1023;
                int i = r >> 4, b = r & 15;
                float4 v = *(const float4*)&in[(((size_t)(b0+b)*3 + cc)*DI + i)*DT + (t+1)];
                s->in4[((cc*4+0)*DI + i)*NB + b] = v.x;
                s->in4[((cc*4+1)*DI + i)*NB + b] = v.y;
                s->in4[((cc*4+2)*DI + i)*NB + b] = v.z;
                s->in4[((cc*4+3)*DI + i)*NB + b] = v.w;
            }
        }
        __syncthreads();

        // ---- arrive at grid barrier, then Phase A(t+1) in its shadow ----
        if (tid == 0) { __threadfence(); atomicAdd(&d_bar[t], 1u); }

        if ((t+1) < DT) {
            const int u1 = (t+1) & 3;
            const ulonglong2* DD = (const ulonglong2*)&s->in4[(2*4+u1)*DI*NB];
            if (tid < 256) {
                int jp = tid & 31, bq = (tid>>5)&1, ks = tid>>6;
                ull A[8] = {0,0,0,0,0,0,0,0};
                accG<128>((const float2*)d_wdghT, rank*32 + jp, DD, bq, ks*16, ks*16+16, A);
                stP(s, tid, A);
            } else if (tid < 384) {
                int idx = tid - 256;
                int ip = idx & 7, bq = (idx>>3)&1, ks = idx>>4;
                ull A[8] = {0,0,0,0,0,0,0,0};
                accG<32>((const float2*)d_wdgxT, rank*8 + ip, DD, bq, ks*8, ks*8+8, A);
                stP(s, tid, A);
            }
        }
        __syncthreads();
        if ((t+1) < DT) {
            const int u1 = (t+1) & 3;
            const int par = (t+1) & 1;
            const float* Xc = &s->in4[(0*4+u1)*DI*NB];
            const float* Mc = &s->in4[(1*4+u1)*DI*NB];
            #pragma unroll
            for (int hf = 0; hf < 2; hf++) {
                int idx = hf*TPB + tid;
                int b = idx & 15, j = idx >> 4;
                int jp = j >> 1, lo = j & 1, bq = b >> 3, bo = b & 7;
                float f = 0.f;
                #pragma unroll
                for (int ks = 0; ks < 4; ks++)
                    f += PF[(ks*64 + bq*32 + jp)*PSF + lo*8 + bo];
                s->gbuf[j*NB + b] = __expf(-fmaxf(f + b_dg_h[colbase + j], 0.f));
            }
            if (tid < 256) {
                int il = tid >> 4, b = tid & 15;
                int ip = il >> 1, lo = il & 1, bq = b >> 3, bo = b & 7;
                int ig = rank*16 + il;
                float f = 0.f;
                #pragma unroll
                for (int ks = 0; ks < 8; ks++)
                    f += PF[(256 + ks*16 + bq*8 + ip)*PSF + lo*8 + bo];
                float gg = __expf(-fmaxf(f + b_dg_x[ig], 0.f));
                float mm = Mc[ig*NB + b], xx = Xc[ig*NB + b];
                float xl = (mm > 0.f) ? xx : s->xlast[il*NB + b];
                s->xlast[il*NB + b] = xl;
                float xv = mm*xx + (1.f-mm)*(gg*xl + (1.f-gg)*x_mean[ig]);
                s->ximp[par][ig*NB + b] = xv;
                uint32_t la = s2u(&s->ximp[par][ig*NB + b]);
                #pragma unroll
                for (int r = 0; r < CSZ; r++)
                    if (r != rank) stc1(mapa_(la, (uint32_t)r), xv);
                s->xo4[(il*NB + b)*4 + u1] = xv;
                if (u1 == 3)
                    *(float4*)&out_x[((size_t)(b0+b)*DI + ig)*DT + (t+1) - 3] =
                        *(const float4*)&s->xo4[(il*NB + b)*4];
            }
        }
        __syncthreads();

        // ---- wait for all CTAs ----
        if (tid == 0) {
            while (*(volatile unsigned*)&d_bar[t] < (unsigned)NBLK) { __nanosleep(32); }
            __threadfence();
        }
        __syncthreads();

        // ---- Phase D: BN stats (128 threads: j x half, shfl merge) ----
        if (tid < 128) {
            int j = tid >> 1, hf = tid & 1;
            int jg = colbase + j, buf = t & 1;
            const float4* ps = (const float4*)d_psum[buf][jg] + hf*4;
            const float4* pq = (const float4*)d_psq [buf][jg] + hf*4;
            float s1 = 0.f, s2 = 0.f;
            #pragma unroll
            for (int pp = 0; pp < 4; pp++) {
                float4 a4 = __ldcg(ps + pp);
                float4 c4 = __ldcg(pq + pp);
                s1 += (a4.x + a4.y) + (a4.z + a4.w);
                s2 += (c4.x + c4.y) + (c4.z + c4.w);
            }
            s1 += __shfl_xor_sync(0xffffffffu, s1, 1);
            s2 += __shfl_xor_sync(0xffffffffu, s2, 1);
            if (hf == 0) {
                float mu  = s1 * (1.f/(float)DB);
                float var = fmaf(s2, 1.f/(float)DB, -mu*mu);
                float rs  = rsqrtf(var + 1e-5f);
                float aa  = rs * bn_g[jg];
                s->a[j] = aa;
                s->c[j] = fmaf(-mu, aa, bn_b[jg]);
            }
        }
        __syncthreads();

        // ---- Phase E: normalize, carry h, coalesced out_h, hdec(t+1) ----
        if (tid < 256) {
            int bq4 = tid >> 6, j = tid & 63, jg = colbase + j;
            float aa = s->a[j], cc = s->c[j];
            float4 hd4; float* hp = (float*)&hd4;
            #pragma unroll
            for (int u2 = 0; u2 < 4; u2++) {
                int b = bq4*4 + u2;
                float hb = fmaf(s->hnew[j*HST + b], aa, cc);
                s->h[j*HST + b] = hb;
                out_h[((size_t)(b0+b)*DT + t)*DH + jg] = hb;
                hp[u2] = s->gbuf[j*NB + b] * hb;
            }
            *(float4*)&s->hdec[jg*NB + bq4*4] = hd4;
            uint32_t la = s2u(&s->hdec[jg*NB + bq4*4]);
            #pragma unroll
            for (int r = 0; r < CSZ; r++)
                if (r != rank) stc4(mapa_(la, (uint32_t)r), hd4);
        }
        CLUSTER_SYNC();   // hdec + ximp exchanges complete (full block barrier)
    }

    // -------- epilogue: y = sigmoid(h @ w_hy^T + b) from out_h --------
    __threadfence();
    CLUSTER_SYNC();          // peers' out_h STG visible
    {
        float* swhy = s->z;  // 512-float cache
        if (tid < DO*DH) swhy[tid] = w_hy[tid];
        __syncthreads();
        float bhy0 = b_hy[0], bhy1 = b_hy[1];
        int w = tid >> 5, lane = tid & 31;
        for (int task = w; task < 4*DT*DO; task += 16) {
            int t = task >> 3, sub = task & 7;
            int lb = sub >> 1, o = sub & 1;
            int b = b0 + rank*4 + lb;
            const float* hrow = out_h + ((size_t)b*DT + t)*DH;
            float acc = 0.f;
            #pragma unroll
            for (int kk = 0; kk < 8; kk++)
                acc = fmaf(__ldcg(&hrow[lane + kk*32]), swhy[o*DH + lane + kk*32], acc);
            #pragma unroll
            for (int off = 16; off; off >>= 1)
                acc += __shfl_xor_sync(0xffffffffu, acc, off);
            if (lane == 0)
                out_y[((size_t)b*DT + t)*DO + o] =
                    1.f / (1.f + expf(-(acc + (o ? bhy1 : bhy0))));
        }
    }
}

extern "C" void kernel_launch(void* const* d_in, const int* in_sizes, int n_in,
                              void* d_out, int out_size) {
    cudaFuncSetAttribute(grud_kernel, cudaFuncAttributeMaxDynamicSharedMemorySize,
                         (int)sizeof(Smem));
    grud_kernel<<<NBLK, TPB, sizeof(Smem)>>>(
        (const float*)d_in[0],  (const float*)d_in[1],
        (const float*)d_in[2],  (const float*)d_in[3],
        (const float*)d_in[4],  (const float*)d_in[5],
        (const float*)d_in[6],  (const float*)d_in[7],
        (const float*)d_in[8],  (const float*)d_in[9],
        (const float*)d_in[10], (const float*)d_in[11],
        (const float*)d_in[12], (const float*)d_in[13],
        (const float*)d_in[14], (const float*)d_in[15],
        (const float*)d_in[16], (const float*)d_in[17],
        (const float*)d_in[18], (const float*)d_in[19],
        (const float*)d_in[20], (const float*)d_in[21],
        (float*)d_out);
}